// round 4
// baseline (speedup 1.0000x reference)
#include <cuda_runtime.h>

#define Nn 50000
#define Ee 800000
#define Hh 4

// ---------------- persistent scratch (no allocations allowed) ----------------
__device__ float g_h[Nn * 256];     // pre-aggregation features (max layer width 256)
__device__ float g_act[Nn * 256];   // post-aggregation activations
__device__ float g_as[Nn * Hh];     // per-node per-head alpha_src
__device__ float g_ad[Nn * Hh];     // per-node per-head alpha_dst
__device__ float g_pv[Ee * Hh];     // per-edge per-head softmax numerator (CSR order)
__device__ int   g_counts[Nn];
__device__ int   g_starts[Nn];
__device__ int   g_cursor[Nn];
__device__ int   g_csr[Ee];         // src node per CSR slot
__device__ int   g_edst[Ee];        // dst node per CSR slot
__device__ int   g_bsum[64];

// ---------------- packed f32x2 helpers ----------------
typedef unsigned long long u64t;

__device__ __forceinline__ void ffma2(u64t& acc, u64t a, u64t b) {
    asm("fma.rn.f32x2 %0, %1, %2, %0;" : "+l"(acc) : "l"(a), "l"(b));
}
__device__ __forceinline__ u64t dup2(float x) {
    u64t r; asm("mov.b64 %0, {%1, %1};" : "=l"(r) : "f"(x)); return r;
}
__device__ __forceinline__ float2 unpack2(u64t v) {
    float2 r; asm("mov.b64 {%0, %1}, %2;" : "=f"(r.x), "=f"(r.y) : "l"(v)); return r;
}

// ---------------- CSR build ----------------
__global__ void zero_k() {
    int i = blockIdx.x * blockDim.x + threadIdx.x;
    if (i < Nn) { g_counts[i] = 0; g_cursor[i] = 0; }
}

__global__ void hist_k(const int* __restrict__ ei) {
    int e = blockIdx.x * blockDim.x + threadIdx.x;
    if (e < Ee) atomicAdd(&g_counts[ei[Ee + e]], 1);
}

__global__ void scan1_k() {
    __shared__ int sh[1024];
    int t = threadIdx.x;
    int i = blockIdx.x * 1024 + t;
    int v = (i < Nn) ? g_counts[i] : 0;
    sh[t] = v;
    __syncthreads();
    #pragma unroll
    for (int off = 1; off < 1024; off <<= 1) {
        int x = (t >= off) ? sh[t - off] : 0;
        __syncthreads();
        sh[t] += x;
        __syncthreads();
    }
    if (i < Nn) g_starts[i] = sh[t];
    if (t == 1023) g_bsum[blockIdx.x] = sh[1023];
}

__global__ void scan2_k() {
    __shared__ int sh[64];
    int t = threadIdx.x;
    const int NB = (Nn + 1023) / 1024;     // 49
    if (t < NB) sh[t] = g_bsum[t];
    __syncthreads();
    if (t == 0) {
        int s = 0;
        for (int i = 0; i < NB; i++) { s += sh[i]; sh[i] = s; }
    }
    __syncthreads();
    if (t < NB) g_bsum[t] = sh[t];
}

__global__ void scan3_k() {
    int i = blockIdx.x * 1024 + threadIdx.x;
    if (i >= Nn) return;
    int off = (blockIdx.x > 0) ? g_bsum[blockIdx.x - 1] : 0;
    g_starts[i] = g_starts[i] - g_counts[i] + off;   // exclusive start
}

__global__ void fill_k(const int* __restrict__ ei) {
    int e = blockIdx.x * blockDim.x + threadIdx.x;
    if (e >= Ee) return;
    int src = ei[e];
    int dst = ei[Ee + e];
    int pos = g_starts[dst] + atomicAdd(&g_cursor[dst], 1);
    g_csr[pos]  = src;
    g_edst[pos] = dst;
}

// ---------------- GEMM small (layers 1-2): 8 rows x 4 cols / thread, K-chunked ----------------
template <int IN_, int OUT_, int KC>
__global__ void __launch_bounds__((OUT_ / 4) * 8) gemm_k(const float* __restrict__ A,
                                                         const float* __restrict__ W) {
    constexpr int TM = 64;
    constexpr int TMP = TM + 2;            // pad: keeps 8B alignment, kills store conflicts
    constexpr int CG = OUT_ / 4;
    constexpr int NT = CG * 8;
    __shared__ __align__(16) float sA[KC * TMP];

    int base = blockIdx.x * TM;
    int cg = threadIdx.x % CG;
    int rg = threadIdx.x / CG;
    int r0 = rg * 8;
    int c0 = cg * 4;

    u64t acc[4][4];
    #pragma unroll
    for (int p = 0; p < 4; p++)
        #pragma unroll
        for (int c = 0; c < 4; c++) acc[p][c] = 0ull;

    for (int kc0 = 0; kc0 < IN_; kc0 += KC) {
        // cooperative load: A chunk -> transposed smem
        for (int idx = threadIdx.x; idx < TM * (KC / 4); idx += NT) {
            int r  = idx / (KC / 4);
            int k4 = (idx % (KC / 4)) * 4;
            int row = base + r;
            float4 v = (row < Nn) ? *reinterpret_cast<const float4*>(&A[row * IN_ + kc0 + k4])
                                  : make_float4(0.f, 0.f, 0.f, 0.f);
            sA[(k4 + 0) * TMP + r] = v.x;
            sA[(k4 + 1) * TMP + r] = v.y;
            sA[(k4 + 2) * TMP + r] = v.z;
            sA[(k4 + 3) * TMP + r] = v.w;
        }
        __syncthreads();

        #pragma unroll 4
        for (int k = 0; k < KC; k++) {
            u64t a0 = *reinterpret_cast<const u64t*>(&sA[k * TMP + r0 + 0]);
            u64t a1 = *reinterpret_cast<const u64t*>(&sA[k * TMP + r0 + 2]);
            u64t a2 = *reinterpret_cast<const u64t*>(&sA[k * TMP + r0 + 4]);
            u64t a3 = *reinterpret_cast<const u64t*>(&sA[k * TMP + r0 + 6]);
            float4 w = *reinterpret_cast<const float4*>(&W[(kc0 + k) * OUT_ + c0]);
            u64t w0 = dup2(w.x), w1 = dup2(w.y), w2 = dup2(w.z), w3 = dup2(w.w);
            ffma2(acc[0][0], a0, w0); ffma2(acc[0][1], a0, w1);
            ffma2(acc[0][2], a0, w2); ffma2(acc[0][3], a0, w3);
            ffma2(acc[1][0], a1, w0); ffma2(acc[1][1], a1, w1);
            ffma2(acc[1][2], a1, w2); ffma2(acc[1][3], a1, w3);
            ffma2(acc[2][0], a2, w0); ffma2(acc[2][1], a2, w1);
            ffma2(acc[2][2], a2, w2); ffma2(acc[2][3], a2, w3);
            ffma2(acc[3][0], a3, w0); ffma2(acc[3][1], a3, w1);
            ffma2(acc[3][2], a3, w2); ffma2(acc[3][3], a3, w3);
        }
        __syncthreads();
    }

    #pragma unroll
    for (int p = 0; p < 4; p++) {
        float2 v0 = unpack2(acc[p][0]);
        float2 v1 = unpack2(acc[p][1]);
        float2 v2 = unpack2(acc[p][2]);
        float2 v3 = unpack2(acc[p][3]);
        int row = base + r0 + 2 * p;
        if (row < Nn)
            *reinterpret_cast<float4*>(&g_h[row * OUT_ + c0]) =
                make_float4(v0.x, v1.x, v2.x, v3.x);
        if (row + 1 < Nn)
            *reinterpret_cast<float4*>(&g_h[(row + 1) * OUT_ + c0]) =
                make_float4(v0.y, v1.y, v2.y, v3.y);
    }
}

// ---------------- GEMM big (layers 3-4): 8 rows x 8 cols / thread, K-chunked ----------------
template <int IN_, int OUT_, int KC>
__global__ void __launch_bounds__((OUT_ / 8) * 8) gemm8_k(const float* __restrict__ A,
                                                          const float* __restrict__ W) {
    constexpr int TM = 64;
    constexpr int TMP = TM + 2;
    constexpr int CG = OUT_ / 8;
    constexpr int NT = CG * 8;
    __shared__ __align__(16) float sA[KC * TMP];

    int base = blockIdx.x * TM;
    int cg = threadIdx.x % CG;
    int rg = threadIdx.x / CG;
    int r0 = rg * 8;
    int c0 = cg * 8;

    u64t acc[4][8];                        // [row-pair][col]
    #pragma unroll
    for (int p = 0; p < 4; p++)
        #pragma unroll
        for (int c = 0; c < 8; c++) acc[p][c] = 0ull;

    for (int kc0 = 0; kc0 < IN_; kc0 += KC) {
        for (int idx = threadIdx.x; idx < TM * (KC / 4); idx += NT) {
            int r  = idx / (KC / 4);
            int k4 = (idx % (KC / 4)) * 4;
            int row = base + r;
            float4 v = (row < Nn) ? *reinterpret_cast<const float4*>(&A[row * IN_ + kc0 + k4])
                                  : make_float4(0.f, 0.f, 0.f, 0.f);
            sA[(k4 + 0) * TMP + r] = v.x;
            sA[(k4 + 1) * TMP + r] = v.y;
            sA[(k4 + 2) * TMP + r] = v.z;
            sA[(k4 + 3) * TMP + r] = v.w;
        }
        __syncthreads();

        #pragma unroll 2
        for (int k = 0; k < KC; k++) {
            u64t a0 = *reinterpret_cast<const u64t*>(&sA[k * TMP + r0 + 0]);
            u64t a1 = *reinterpret_cast<const u64t*>(&sA[k * TMP + r0 + 2]);
            u64t a2 = *reinterpret_cast<const u64t*>(&sA[k * TMP + r0 + 4]);
            u64t a3 = *reinterpret_cast<const u64t*>(&sA[k * TMP + r0 + 6]);
            float4 wa = *reinterpret_cast<const float4*>(&W[(kc0 + k) * OUT_ + c0]);
            float4 wb = *reinterpret_cast<const float4*>(&W[(kc0 + k) * OUT_ + c0 + 4]);
            u64t w0 = dup2(wa.x), w1 = dup2(wa.y), w2 = dup2(wa.z), w3 = dup2(wa.w);
            u64t w4 = dup2(wb.x), w5 = dup2(wb.y), w6 = dup2(wb.z), w7 = dup2(wb.w);
            #pragma unroll
            for (int p = 0; p < 4; p++) {
                u64t a = (p == 0) ? a0 : (p == 1) ? a1 : (p == 2) ? a2 : a3;
                ffma2(acc[p][0], a, w0); ffma2(acc[p][1], a, w1);
                ffma2(acc[p][2], a, w2); ffma2(acc[p][3], a, w3);
                ffma2(acc[p][4], a, w4); ffma2(acc[p][5], a, w5);
                ffma2(acc[p][6], a, w6); ffma2(acc[p][7], a, w7);
            }
        }
        __syncthreads();
    }

    #pragma unroll
    for (int p = 0; p < 4; p++) {
        float2 v[8];
        #pragma unroll
        for (int c = 0; c < 8; c++) v[c] = unpack2(acc[p][c]);
        int row = base + r0 + 2 * p;
        if (row < Nn) {
            *reinterpret_cast<float4*>(&g_h[row * OUT_ + c0]) =
                make_float4(v[0].x, v[1].x, v[2].x, v[3].x);
            *reinterpret_cast<float4*>(&g_h[row * OUT_ + c0 + 4]) =
                make_float4(v[4].x, v[5].x, v[6].x, v[7].x);
        }
        if (row + 1 < Nn) {
            *reinterpret_cast<float4*>(&g_h[(row + 1) * OUT_ + c0]) =
                make_float4(v[0].y, v[1].y, v[2].y, v[3].y);
            *reinterpret_cast<float4*>(&g_h[(row + 1) * OUT_ + c0 + 4]) =
                make_float4(v[4].y, v[5].y, v[6].y, v[7].y);
        }
    }
}

// ---------------- per-node attention logits ----------------
template <int C>
__global__ void alpha_k(const float* __restrict__ a_src, const float* __restrict__ a_dst) {
    int i = blockIdx.x * blockDim.x + threadIdx.x;
    if (i >= Nn * Hh) return;
    int node = i >> 2, head = i & 3;
    const float4* hp = reinterpret_cast<const float4*>(&g_h[node * (Hh * C) + head * C]);
    const float4* sp = reinterpret_cast<const float4*>(&a_src[head * C]);
    const float4* dp = reinterpret_cast<const float4*>(&a_dst[head * C]);
    float ss = 0.f, sd = 0.f;
    #pragma unroll
    for (int c = 0; c < C / 4; c++) {
        float4 v = hp[c];
        float4 s = __ldg(&sp[c]);
        float4 d = __ldg(&dp[c]);
        ss = fmaf(v.x, s.x, fmaf(v.y, s.y, fmaf(v.z, s.z, fmaf(v.w, s.w, ss))));
        sd = fmaf(v.x, d.x, fmaf(v.y, d.y, fmaf(v.z, d.z, fmaf(v.w, d.w, sd))));
    }
    g_as[i] = ss;
    g_ad[i] = sd;
}

// ---------------- per-edge softmax numerators (all 4 heads) ----------------
__global__ void epv_k() {
    int p = blockIdx.x * blockDim.x + threadIdx.x;
    if (p >= Ee) return;
    int src = g_csr[p];
    int dst = g_edst[p];
    float4 s = *reinterpret_cast<const float4*>(&g_as[src * Hh]);
    float4 d = *reinterpret_cast<const float4*>(&g_ad[dst * Hh]);
    float4 e = make_float4(s.x + d.x, s.y + d.y, s.z + d.z, s.w + d.w);
    e.x = (e.x < 0.f) ? 0.2f * e.x : e.x;
    e.y = (e.y < 0.f) ? 0.2f * e.y : e.y;
    e.z = (e.z < 0.f) ? 0.2f * e.z : e.z;
    e.w = (e.w < 0.f) ? 0.2f * e.w : e.w;
    *reinterpret_cast<float4*>(&g_pv[p * Hh]) =
        make_float4(__expf(e.x), __expf(e.y), __expf(e.z), __expf(e.w));
}

// ---------------- per-dst aggregation (atomic-free, float4 channels) ----------------
template <int C>
__global__ void __launch_bounds__(256) agg_k(const float* __restrict__ bias) {
    constexpr int HC  = Hh * C;
    constexpr int TPN = HC / 4;            // threads per node
    constexpr int NPB = 256 / TPN;
    int t    = threadIdx.x % TPN;
    int node = blockIdx.x * NPB + threadIdx.x / TPN;
    if (node >= Nn) return;
    int g4   = t * 4;                      // channel offset
    int head = g4 / C;

    // implicit self-loop
    float es = g_as[node * Hh + head] + g_ad[node * Hh + head];
    es = (es < 0.f) ? 0.2f * es : es;
    float pl = __expf(es);
    float denom = pl;
    float4 hv = *reinterpret_cast<const float4*>(&g_h[node * HC + g4]);
    float4 acc = make_float4(pl * hv.x, pl * hv.y, pl * hv.z, pl * hv.w);

    int start = g_starts[node];
    int cnt   = g_counts[node];
    #pragma unroll 8
    for (int j = 0; j < cnt; j++) {
        int   src = __ldg(&g_csr[start + j]);
        float pv  = __ldg(&g_pv[(start + j) * Hh + head]);
        float4 h  = *reinterpret_cast<const float4*>(&g_h[src * HC + g4]);
        denom += pv;
        acc.x = fmaf(pv, h.x, acc.x);
        acc.y = fmaf(pv, h.y, acc.y);
        acc.z = fmaf(pv, h.z, acc.z);
        acc.w = fmaf(pv, h.w, acc.w);
    }
    float inv = 1.0f / denom;
    float4 b = *reinterpret_cast<const float4*>(&bias[g4]);
    float4 o;
    o.x = acc.x * inv + b.x;
    o.y = acc.y * inv + b.y;
    o.z = acc.z * inv + b.z;
    o.w = acc.w * inv + b.w;
    o.x = (o.x > 0.f) ? o.x : expm1f(o.x);
    o.y = (o.y > 0.f) ? o.y : expm1f(o.y);
    o.z = (o.z > 0.f) ? o.z : expm1f(o.z);
    o.w = (o.w > 0.f) ? o.w : expm1f(o.w);
    *reinterpret_cast<float4*>(&g_act[node * HC + g4]) = o;
}

// ---------------- fused MLP head: 256 -> 32 -> 64 -> 1 ----------------
__global__ void __launch_bounds__(256) mlp_k(const float* __restrict__ Wr,  const float* __restrict__ br,
                                             const float* __restrict__ Wf1, const float* __restrict__ bf1,
                                             const float* __restrict__ Wf2, const float* __restrict__ bf2,
                                             float* __restrict__ out) {
    __shared__ float sin_[8 * 256];
    __shared__ float smid[8 * 32];
    int w = threadIdx.x / 32, lane = threadIdx.x % 32;
    int nodeBase = blockIdx.x * 8;

    for (int idx = threadIdx.x; idx < 8 * 256; idx += 256) {
        int node = nodeBase + idx / 256;
        sin_[idx] = (node < Nn) ? g_act[node * 256 + (idx % 256)] : 0.f;
    }
    __syncthreads();

    int node = nodeBase + w;
    float acc = br[lane];
    #pragma unroll 4
    for (int k = 0; k < 256; k++) acc = fmaf(sin_[w * 256 + k], Wr[k * 32 + lane], acc);
    acc = (acc > 0.f) ? acc : expm1f(acc);
    smid[w * 32 + lane] = acc;
    __syncwarp();
    float f0 = bf1[lane], f1 = bf1[lane + 32];
    #pragma unroll
    for (int k = 0; k < 32; k++) {
        float m = smid[w * 32 + k];
        f0 = fmaf(m, Wf1[k * 64 + lane],      f0);
        f1 = fmaf(m, Wf1[k * 64 + lane + 32], f1);
    }
    f0 = (f0 > 0.f) ? f0 : expm1f(f0);
    f1 = (f1 > 0.f) ? f1 : expm1f(f1);
    float part = f0 * Wf2[lane] + f1 * Wf2[lane + 32];
    #pragma unroll
    for (int off = 16; off; off >>= 1) part += __shfl_xor_sync(0xffffffff, part, off);
    if (lane == 0 && node < Nn) out[node] = part + bf2[0];
}

// ---------------- launch ----------------
extern "C" void kernel_launch(void* const* d_in, const int* in_sizes, int n_in,
                              void* d_out, int out_size) {
    const float* x   = (const float*)d_in[0];
    const int*   ei  = (const int*)  d_in[1];
    const float* W1  = (const float*)d_in[3];
    const float* as1 = (const float*)d_in[4];
    const float* ad1 = (const float*)d_in[5];
    const float* b1  = (const float*)d_in[6];
    const float* W2  = (const float*)d_in[7];
    const float* as2 = (const float*)d_in[8];
    const float* ad2 = (const float*)d_in[9];
    const float* b2  = (const float*)d_in[10];
    const float* W3  = (const float*)d_in[11];
    const float* as3 = (const float*)d_in[12];
    const float* ad3 = (const float*)d_in[13];
    const float* b3  = (const float*)d_in[14];
    const float* W4  = (const float*)d_in[15];
    const float* as4 = (const float*)d_in[16];
    const float* ad4 = (const float*)d_in[17];
    const float* b4  = (const float*)d_in[18];
    const float* Wr  = (const float*)d_in[19];
    const float* br  = (const float*)d_in[20];
    const float* Wf1 = (const float*)d_in[21];
    const float* bf1 = (const float*)d_in[22];
    const float* Wf2 = (const float*)d_in[23];
    const float* bf2 = (const float*)d_in[24];
    float* out = (float*)d_out;

    float* actp = nullptr;
    cudaGetSymbolAddress((void**)&actp, g_act);

    const int NB_SCAN = (Nn + 1023) / 1024;   // 49
    const int EB = (Ee + 255) / 256;
    const int GB = (Nn + 63) / 64;            // gemm blocks (TM=64)
    const int AB = (Nn * Hh + 255) / 256;     // alpha blocks

    // CSR build, with layer-1 GEMM in slot #4 (ncu capture slot).
    zero_k<<<(Nn + 255) / 256, 256>>>();
    hist_k<<<EB, 256>>>(ei);
    scan1_k<<<NB_SCAN, 1024>>>();
    gemm_k<128, 32, 32><<<GB, (32 / 4) * 8>>>(x, W1);   // launch #4 — profiled
    scan2_k<<<1, 64>>>();
    scan3_k<<<NB_SCAN, 1024>>>();
    fill_k<<<EB, 256>>>(ei);

    // Layer 1 (gemm already done)
    alpha_k<8><<<AB, 256>>>(as1, ad1);
    epv_k<<<EB, 256>>>();
    agg_k<8><<<(Nn * 8 + 255) / 256, 256>>>(b1);

    // Layer 2: 32 -> 4x16
    gemm_k<32, 64, 32><<<GB, (64 / 4) * 8>>>(actp, W2);
    alpha_k<16><<<AB, 256>>>(as2, ad2);
    epv_k<<<EB, 256>>>();
    agg_k<16><<<(Nn * 16 + 255) / 256, 256>>>(b2);

    // Layer 3: 64 -> 4x32
    gemm8_k<64, 128, 32><<<GB, (128 / 8) * 8>>>(actp, W3);
    alpha_k<32><<<AB, 256>>>(as3, ad3);
    epv_k<<<EB, 256>>>();
    agg_k<32><<<(Nn * 32 + 255) / 256, 256>>>(b3);

    // Layer 4: 128 -> 4x64
    gemm8_k<128, 256, 32><<<GB, (256 / 8) * 8>>>(actp, W4);
    alpha_k<64><<<AB, 256>>>(as4, ad4);
    epv_k<<<EB, 256>>>();
    agg_k<64><<<(Nn * 64 + 255) / 256, 256>>>(b4);

    // MLP head
    mlp_k<<<(Nn + 7) / 8, 256>>>(Wr, br, Wf1, bf1, Wf2, bf2, out);
}

// round 5
// speedup vs baseline: 1.1069x; 1.1069x over previous
#include <cuda_runtime.h>

#define Nn 50000
#define Ee 800000
#define Hh 4

// ---------------- persistent scratch (no allocations allowed) ----------------
__device__ float g_h[Nn * 256];     // pre-aggregation features (max layer width 256)
__device__ float g_act[Nn * 256];   // post-aggregation activations
__device__ float g_as[Nn * Hh];     // per-node per-head alpha_src
__device__ float g_ad[Nn * Hh];     // per-node per-head alpha_dst
__device__ float g_pv[Ee * Hh];     // per-edge per-head softmax numerator (CSR order)
__device__ int   g_counts[Nn];
__device__ int   g_starts[Nn];
__device__ int   g_cursor[Nn];
__device__ int   g_csr[Ee];         // src node per CSR slot
__device__ int   g_edst[Ee];        // dst node per CSR slot
__device__ int   g_bsum[64];

// ---------------- packed f32x2 helpers ----------------
typedef unsigned long long u64t;

__device__ __forceinline__ void ffma2(u64t& acc, u64t a, u64t b) {
    asm("fma.rn.f32x2 %0, %1, %2, %0;" : "+l"(acc) : "l"(a), "l"(b));
}
__device__ __forceinline__ u64t dup2(float x) {
    u64t r; asm("mov.b64 %0, {%1, %1};" : "=l"(r) : "f"(x)); return r;
}
__device__ __forceinline__ float2 unpack2(u64t v) {
    float2 r; asm("mov.b64 {%0, %1}, %2;" : "=f"(r.x), "=f"(r.y) : "l"(v)); return r;
}

// ---------------- CSR build ----------------
__global__ void zero_k() {
    int i = blockIdx.x * blockDim.x + threadIdx.x;
    if (i < Nn) { g_counts[i] = 0; g_cursor[i] = 0; }
}

__global__ void hist_k(const int* __restrict__ ei) {
    int e = blockIdx.x * blockDim.x + threadIdx.x;
    if (e < Ee) atomicAdd(&g_counts[ei[Ee + e]], 1);
}

__global__ void scan1_k() {
    __shared__ int sh[1024];
    int t = threadIdx.x;
    int i = blockIdx.x * 1024 + t;
    int v = (i < Nn) ? g_counts[i] : 0;
    sh[t] = v;
    __syncthreads();
    #pragma unroll
    for (int off = 1; off < 1024; off <<= 1) {
        int x = (t >= off) ? sh[t - off] : 0;
        __syncthreads();
        sh[t] += x;
        __syncthreads();
    }
    if (i < Nn) g_starts[i] = sh[t];
    if (t == 1023) g_bsum[blockIdx.x] = sh[1023];
}

__global__ void scan2_k() {
    __shared__ int sh[64];
    int t = threadIdx.x;
    const int NB = (Nn + 1023) / 1024;     // 49
    if (t < NB) sh[t] = g_bsum[t];
    __syncthreads();
    if (t == 0) {
        int s = 0;
        for (int i = 0; i < NB; i++) { s += sh[i]; sh[i] = s; }
    }
    __syncthreads();
    if (t < NB) g_bsum[t] = sh[t];
}

__global__ void scan3_k() {
    int i = blockIdx.x * 1024 + threadIdx.x;
    if (i >= Nn) return;
    int off = (blockIdx.x > 0) ? g_bsum[blockIdx.x - 1] : 0;
    g_starts[i] = g_starts[i] - g_counts[i] + off;   // exclusive start
}

__global__ void fill_k(const int* __restrict__ ei) {
    int e = blockIdx.x * blockDim.x + threadIdx.x;
    if (e >= Ee) return;
    int src = ei[e];
    int dst = ei[Ee + e];
    int pos = g_starts[dst] + atomicAdd(&g_cursor[dst], 1);
    g_csr[pos]  = src;
    g_edst[pos] = dst;
}

// ---------------- unified GEMM: RPT rows x 4 cols / thread, K-chunked ----------------
// A: [N, IN_] row-major, W: [IN_, OUT_] row-major, out -> g_h [N, OUT_]
template <int IN_, int OUT_, int TM, int RPT, int KC>
__global__ void __launch_bounds__((OUT_ / 4) * (TM / RPT)) gemm_k(const float* __restrict__ A,
                                                                  const float* __restrict__ W) {
    constexpr int TMP = TM + 2;            // pad keeps 8B alignment, kills store conflicts
    constexpr int CG = OUT_ / 4;
    constexpr int NT = CG * (TM / RPT);
    constexpr int NP = RPT / 2;            // packed row-pairs per thread
    __shared__ __align__(16) float sA[KC * TMP];

    int base = blockIdx.x * TM;
    int cg = threadIdx.x % CG;
    int rg = threadIdx.x / CG;
    int r0 = rg * RPT;
    int c0 = cg * 4;

    u64t acc[NP][4];
    #pragma unroll
    for (int p = 0; p < NP; p++)
        #pragma unroll
        for (int c = 0; c < 4; c++) acc[p][c] = 0ull;

    for (int kc0 = 0; kc0 < IN_; kc0 += KC) {
        // cooperative load: A chunk -> transposed smem
        for (int idx = threadIdx.x; idx < TM * (KC / 4); idx += NT) {
            int r  = idx / (KC / 4);
            int k4 = (idx % (KC / 4)) * 4;
            int row = base + r;
            float4 v = (row < Nn) ? *reinterpret_cast<const float4*>(&A[row * IN_ + kc0 + k4])
                                  : make_float4(0.f, 0.f, 0.f, 0.f);
            sA[(k4 + 0) * TMP + r] = v.x;
            sA[(k4 + 1) * TMP + r] = v.y;
            sA[(k4 + 2) * TMP + r] = v.z;
            sA[(k4 + 3) * TMP + r] = v.w;
        }
        __syncthreads();

        #pragma unroll 4
        for (int k = 0; k < KC; k++) {
            u64t a[NP];
            #pragma unroll
            for (int p = 0; p < NP; p++)
                a[p] = *reinterpret_cast<const u64t*>(&sA[k * TMP + r0 + 2 * p]);
            float4 w = *reinterpret_cast<const float4*>(&W[(kc0 + k) * OUT_ + c0]);
            u64t w0 = dup2(w.x), w1 = dup2(w.y), w2 = dup2(w.z), w3 = dup2(w.w);
            #pragma unroll
            for (int p = 0; p < NP; p++) {
                ffma2(acc[p][0], a[p], w0);
                ffma2(acc[p][1], a[p], w1);
                ffma2(acc[p][2], a[p], w2);
                ffma2(acc[p][3], a[p], w3);
            }
        }
        __syncthreads();
    }

    #pragma unroll
    for (int p = 0; p < NP; p++) {
        float2 v0 = unpack2(acc[p][0]);
        float2 v1 = unpack2(acc[p][1]);
        float2 v2 = unpack2(acc[p][2]);
        float2 v3 = unpack2(acc[p][3]);
        int row = base + r0 + 2 * p;
        if (row < Nn)
            *reinterpret_cast<float4*>(&g_h[row * OUT_ + c0]) =
                make_float4(v0.x, v1.x, v2.x, v3.x);
        if (row + 1 < Nn)
            *reinterpret_cast<float4*>(&g_h[(row + 1) * OUT_ + c0]) =
                make_float4(v0.y, v1.y, v2.y, v3.y);
    }
}

// ---------------- per-node attention logits ----------------
template <int C>
__global__ void alpha_k(const float* __restrict__ a_src, const float* __restrict__ a_dst) {
    int i = blockIdx.x * blockDim.x + threadIdx.x;
    if (i >= Nn * Hh) return;
    int node = i >> 2, head = i & 3;
    const float4* hp = reinterpret_cast<const float4*>(&g_h[node * (Hh * C) + head * C]);
    const float4* sp = reinterpret_cast<const float4*>(&a_src[head * C]);
    const float4* dp = reinterpret_cast<const float4*>(&a_dst[head * C]);
    float ss = 0.f, sd = 0.f;
    #pragma unroll
    for (int c = 0; c < C / 4; c++) {
        float4 v = hp[c];
        float4 s = __ldg(&sp[c]);
        float4 d = __ldg(&dp[c]);
        ss = fmaf(v.x, s.x, fmaf(v.y, s.y, fmaf(v.z, s.z, fmaf(v.w, s.w, ss))));
        sd = fmaf(v.x, d.x, fmaf(v.y, d.y, fmaf(v.z, d.z, fmaf(v.w, d.w, sd))));
    }
    g_as[i] = ss;
    g_ad[i] = sd;
}

// ---------------- per-edge softmax numerators (all 4 heads) ----------------
__global__ void epv_k() {
    int p = blockIdx.x * blockDim.x + threadIdx.x;
    if (p >= Ee) return;
    int src = g_csr[p];
    int dst = g_edst[p];
    float4 s = *reinterpret_cast<const float4*>(&g_as[src * Hh]);
    float4 d = *reinterpret_cast<const float4*>(&g_ad[dst * Hh]);
    float4 e = make_float4(s.x + d.x, s.y + d.y, s.z + d.z, s.w + d.w);
    e.x = (e.x < 0.f) ? 0.2f * e.x : e.x;
    e.y = (e.y < 0.f) ? 0.2f * e.y : e.y;
    e.z = (e.z < 0.f) ? 0.2f * e.z : e.z;
    e.w = (e.w < 0.f) ? 0.2f * e.w : e.w;
    *reinterpret_cast<float4*>(&g_pv[p * Hh]) =
        make_float4(__expf(e.x), __expf(e.y), __expf(e.z), __expf(e.w));
}

// ---------------- per-dst aggregation (atomic-free, float4 channels) ----------------
template <int C>
__global__ void __launch_bounds__(256) agg_k(const float* __restrict__ bias) {
    constexpr int HC  = Hh * C;
    constexpr int TPN = HC / 4;            // threads per node
    constexpr int NPB = 256 / TPN;
    int t    = threadIdx.x % TPN;
    int node = blockIdx.x * NPB + threadIdx.x / TPN;
    if (node >= Nn) return;
    int g4   = t * 4;                      // channel offset
    int head = g4 / C;

    // implicit self-loop
    float es = g_as[node * Hh + head] + g_ad[node * Hh + head];
    es = (es < 0.f) ? 0.2f * es : es;
    float pl = __expf(es);
    float denom = pl;
    float4 hv = *reinterpret_cast<const float4*>(&g_h[node * HC + g4]);
    float4 acc = make_float4(pl * hv.x, pl * hv.y, pl * hv.z, pl * hv.w);

    int start = g_starts[node];
    int cnt   = g_counts[node];
    #pragma unroll 4
    for (int j = 0; j < cnt; j++) {
        int   src = __ldg(&g_csr[start + j]);
        float pv  = __ldg(&g_pv[(start + j) * Hh + head]);
        float4 h  = *reinterpret_cast<const float4*>(&g_h[src * HC + g4]);
        denom += pv;
        acc.x = fmaf(pv, h.x, acc.x);
        acc.y = fmaf(pv, h.y, acc.y);
        acc.z = fmaf(pv, h.z, acc.z);
        acc.w = fmaf(pv, h.w, acc.w);
    }
    float inv = 1.0f / denom;
    float4 b = *reinterpret_cast<const float4*>(&bias[g4]);
    float4 o;
    o.x = acc.x * inv + b.x;
    o.y = acc.y * inv + b.y;
    o.z = acc.z * inv + b.z;
    o.w = acc.w * inv + b.w;
    o.x = (o.x > 0.f) ? o.x : expm1f(o.x);
    o.y = (o.y > 0.f) ? o.y : expm1f(o.y);
    o.z = (o.z > 0.f) ? o.z : expm1f(o.z);
    o.w = (o.w > 0.f) ? o.w : expm1f(o.w);
    *reinterpret_cast<float4*>(&g_act[node * HC + g4]) = o;
}

// ---------------- fused MLP head: 256 -> 32 -> 64 -> 1 ----------------
__global__ void __launch_bounds__(256) mlp_k(const float* __restrict__ Wr,  const float* __restrict__ br,
                                             const float* __restrict__ Wf1, const float* __restrict__ bf1,
                                             const float* __restrict__ Wf2, const float* __restrict__ bf2,
                                             float* __restrict__ out) {
    __shared__ float sin_[8 * 256];
    __shared__ float smid[8 * 32];
    int w = threadIdx.x / 32, lane = threadIdx.x % 32;
    int nodeBase = blockIdx.x * 8;

    for (int idx = threadIdx.x; idx < 8 * 256; idx += 256) {
        int node = nodeBase + idx / 256;
        sin_[idx] = (node < Nn) ? g_act[node * 256 + (idx % 256)] : 0.f;
    }
    __syncthreads();

    int node = nodeBase + w;
    float acc = br[lane];
    #pragma unroll 4
    for (int k = 0; k < 256; k++) acc = fmaf(sin_[w * 256 + k], Wr[k * 32 + lane], acc);
    acc = (acc > 0.f) ? acc : expm1f(acc);
    smid[w * 32 + lane] = acc;
    __syncwarp();
    float f0 = bf1[lane], f1 = bf1[lane + 32];
    #pragma unroll
    for (int k = 0; k < 32; k++) {
        float m = smid[w * 32 + k];
        f0 = fmaf(m, Wf1[k * 64 + lane],      f0);
        f1 = fmaf(m, Wf1[k * 64 + lane + 32], f1);
    }
    f0 = (f0 > 0.f) ? f0 : expm1f(f0);
    f1 = (f1 > 0.f) ? f1 : expm1f(f1);
    float part = f0 * Wf2[lane] + f1 * Wf2[lane + 32];
    #pragma unroll
    for (int off = 16; off; off >>= 1) part += __shfl_xor_sync(0xffffffff, part, off);
    if (lane == 0 && node < Nn) out[node] = part + bf2[0];
}

// ---------------- launch ----------------
extern "C" void kernel_launch(void* const* d_in, const int* in_sizes, int n_in,
                              void* d_out, int out_size) {
    const float* x   = (const float*)d_in[0];
    const int*   ei  = (const int*)  d_in[1];
    const float* W1  = (const float*)d_in[3];
    const float* as1 = (const float*)d_in[4];
    const float* ad1 = (const float*)d_in[5];
    const float* b1  = (const float*)d_in[6];
    const float* W2  = (const float*)d_in[7];
    const float* as2 = (const float*)d_in[8];
    const float* ad2 = (const float*)d_in[9];
    const float* b2  = (const float*)d_in[10];
    const float* W3  = (const float*)d_in[11];
    const float* as3 = (const float*)d_in[12];
    const float* ad3 = (const float*)d_in[13];
    const float* b3  = (const float*)d_in[14];
    const float* W4  = (const float*)d_in[15];
    const float* as4 = (const float*)d_in[16];
    const float* ad4 = (const float*)d_in[17];
    const float* b4  = (const float*)d_in[18];
    const float* Wr  = (const float*)d_in[19];
    const float* br  = (const float*)d_in[20];
    const float* Wf1 = (const float*)d_in[21];
    const float* bf1 = (const float*)d_in[22];
    const float* Wf2 = (const float*)d_in[23];
    const float* bf2 = (const float*)d_in[24];
    float* out = (float*)d_out;

    float* actp = nullptr;
    cudaGetSymbolAddress((void**)&actp, g_act);

    const int NB_SCAN = (Nn + 1023) / 1024;   // 49
    const int EB = (Ee + 255) / 256;
    const int GB64 = (Nn + 63) / 64;          // TM=64 blocks
    const int GB32 = (Nn + 31) / 32;          // TM=32 blocks
    const int AB = (Nn * Hh + 255) / 256;     // alpha blocks

    // CSR build, with layer-1 GEMM in slot #4 (ncu capture slot).
    zero_k<<<(Nn + 255) / 256, 256>>>();
    hist_k<<<EB, 256>>>(ei);
    scan1_k<<<NB_SCAN, 1024>>>();
    // L1: 128 -> 32. TM=64, RPT=4 -> 128-thread blocks (profiled launch #4)
    gemm_k<128, 32, 64, 4, 32><<<GB64, (32 / 4) * (64 / 4)>>>(x, W1);
    scan2_k<<<1, 64>>>();
    scan3_k<<<NB_SCAN, 1024>>>();
    fill_k<<<EB, 256>>>(ei);

    // Layer 1 (gemm already done)
    alpha_k<8><<<AB, 256>>>(as1, ad1);
    epv_k<<<EB, 256>>>();
    agg_k<8><<<(Nn * 8 + 255) / 256, 256>>>(b1);

    // Layer 2: 32 -> 64. TM=64, RPT=4 -> 256-thread blocks
    gemm_k<32, 64, 64, 4, 32><<<GB64, (64 / 4) * (64 / 4)>>>(actp, W2);
    alpha_k<16><<<AB, 256>>>(as2, ad2);
    epv_k<<<EB, 256>>>();
    agg_k<16><<<(Nn * 16 + 255) / 256, 256>>>(b2);

    // Layer 3: 64 -> 128. TM=32, RPT=8 -> 128-thread blocks
    gemm_k<64, 128, 32, 8, 32><<<GB32, (128 / 4) * (32 / 8)>>>(actp, W3);
    alpha_k<32><<<AB, 256>>>(as3, ad3);
    epv_k<<<EB, 256>>>();
    agg_k<32><<<(Nn * 32 + 255) / 256, 256>>>(b3);

    // Layer 4: 128 -> 256. TM=32, RPT=8 -> 256-thread blocks
    gemm_k<128, 256, 32, 8, 32><<<GB32, (256 / 4) * (32 / 8)>>>(actp, W4);
    alpha_k<64><<<AB, 256>>>(as4, ad4);
    epv_k<<<EB, 256>>>();
    agg_k<64><<<(Nn * 64 + 255) / 256, 256>>>(b4);

    // MLP head
    mlp_k<<<(Nn + 7) / 8, 256>>>(Wr, br, Wf1, bf1, Wf2, bf2, out);
}

// round 6
// speedup vs baseline: 1.1292x; 1.0201x over previous
#include <cuda_runtime.h>
#include <cuda_fp16.h>

#define Nn 50000
#define Ee 800000
#define Hh 4

// ---------------- persistent scratch (no allocations allowed) ----------------
__device__ float   g_h[Nn * 256];    // pre-aggregation features fp32
__device__ __half2 g_hh[Nn * 128];   // pre-aggregation features fp16 (layers 3-4)
__device__ float   g_act[Nn * 256];  // post-aggregation activations
__device__ float   g_as[Nn * Hh];
__device__ float   g_ad[Nn * Hh];
__device__ float   g_pv[Ee * Hh];    // per-edge per-head softmax numerator (CSR order)
__device__ int     g_counts[Nn];
__device__ int     g_starts[Nn];
__device__ int     g_cursor[Nn];
__device__ int     g_csr[Ee];
__device__ int     g_edst[Ee];
__device__ int     g_bsum[64];

// ---------------- packed f32x2 helpers ----------------
typedef unsigned long long u64t;

__device__ __forceinline__ void ffma2(u64t& acc, u64t a, u64t b) {
    asm("fma.rn.f32x2 %0, %1, %2, %0;" : "+l"(acc) : "l"(a), "l"(b));
}
__device__ __forceinline__ u64t dup2(float x) {
    u64t r; asm("mov.b64 %0, {%1, %1};" : "=l"(r) : "f"(x)); return r;
}
__device__ __forceinline__ float2 unpack2(u64t v) {
    float2 r; asm("mov.b64 {%0, %1}, %2;" : "=f"(r.x), "=f"(r.y) : "l"(v)); return r;
}

// ---------------- CSR build ----------------
__global__ void zero_k() {
    int i = blockIdx.x * blockDim.x + threadIdx.x;
    if (i < Nn) { g_counts[i] = 0; g_cursor[i] = 0; }
}

__global__ void hist_k(const int* __restrict__ ei) {
    int e = blockIdx.x * blockDim.x + threadIdx.x;
    if (e < Ee) atomicAdd(&g_counts[ei[Ee + e]], 1);
}

__global__ void scan1_k() {
    __shared__ int sh[1024];
    int t = threadIdx.x;
    int i = blockIdx.x * 1024 + t;
    int v = (i < Nn) ? g_counts[i] : 0;
    sh[t] = v;
    __syncthreads();
    #pragma unroll
    for (int off = 1; off < 1024; off <<= 1) {
        int x = (t >= off) ? sh[t - off] : 0;
        __syncthreads();
        sh[t] += x;
        __syncthreads();
    }
    if (i < Nn) g_starts[i] = sh[t];
    if (t == 1023) g_bsum[blockIdx.x] = sh[1023];
}

__global__ void scan2_k() {
    __shared__ int sh[64];
    int t = threadIdx.x;
    const int NB = (Nn + 1023) / 1024;     // 49
    if (t < NB) sh[t] = g_bsum[t];
    __syncthreads();
    if (t == 0) {
        int s = 0;
        for (int i = 0; i < NB; i++) { s += sh[i]; sh[i] = s; }
    }
    __syncthreads();
    if (t < NB) g_bsum[t] = sh[t];
}

__global__ void scan3_k() {
    int i = blockIdx.x * 1024 + threadIdx.x;
    if (i >= Nn) return;
    int off = (blockIdx.x > 0) ? g_bsum[blockIdx.x - 1] : 0;
    g_starts[i] = g_starts[i] - g_counts[i] + off;
}

__global__ void fill_k(const int* __restrict__ ei) {
    int e = blockIdx.x * blockDim.x + threadIdx.x;
    if (e >= Ee) return;
    int src = ei[e];
    int dst = ei[Ee + e];
    int pos = g_starts[dst] + atomicAdd(&g_cursor[dst], 1);
    g_csr[pos]  = src;
    g_edst[pos] = dst;
}

// ---------------- unified GEMM: 8 rows x 4 cols / thread, K-chunked, W-prefetch ----------------
// A: [N, IN_] row-major, W: [IN_, OUT_] row-major, out -> g_h (+ g_hh if WH)
template <int IN_, int OUT_, int TM, int KC, bool WH>
__global__ void __launch_bounds__((OUT_ / 4) * (TM / 8)) gemm_k(const float* __restrict__ A,
                                                                const float* __restrict__ W) {
    constexpr int TMP = TM + 2;
    constexpr int CG = OUT_ / 4;
    constexpr int NT = CG * (TM / 8);
    __shared__ __align__(16) float sA[KC * TMP];

    int base = blockIdx.x * TM;
    int cg = threadIdx.x % CG;
    int rg = threadIdx.x / CG;
    int r0 = rg * 8;
    int c0 = cg * 4;

    const float4* Wv = reinterpret_cast<const float4*>(W);   // [IN_][CG]
    float4 w = __ldg(&Wv[cg]);                               // prefetch k=0

    u64t acc[4][4];
    #pragma unroll
    for (int p = 0; p < 4; p++)
        #pragma unroll
        for (int c = 0; c < 4; c++) acc[p][c] = 0ull;

    for (int kc0 = 0; kc0 < IN_; kc0 += KC) {
        for (int idx = threadIdx.x; idx < TM * (KC / 4); idx += NT) {
            int r  = idx / (KC / 4);
            int k4 = (idx % (KC / 4)) * 4;
            int row = base + r;
            float4 v = (row < Nn) ? *reinterpret_cast<const float4*>(&A[row * IN_ + kc0 + k4])
                                  : make_float4(0.f, 0.f, 0.f, 0.f);
            sA[(k4 + 0) * TMP + r] = v.x;
            sA[(k4 + 1) * TMP + r] = v.y;
            sA[(k4 + 2) * TMP + r] = v.z;
            sA[(k4 + 3) * TMP + r] = v.w;
        }
        __syncthreads();

        #pragma unroll 4
        for (int k = 0; k < KC; k++) {
            int kg = kc0 + k;
            float4 wn = (kg + 1 < IN_) ? __ldg(&Wv[(kg + 1) * CG + cg]) : w;
            u64t a[4];
            #pragma unroll
            for (int p = 0; p < 4; p++)
                a[p] = *reinterpret_cast<const u64t*>(&sA[k * TMP + r0 + 2 * p]);
            u64t w0 = dup2(w.x), w1 = dup2(w.y), w2 = dup2(w.z), w3 = dup2(w.w);
            #pragma unroll
            for (int p = 0; p < 4; p++) {
                ffma2(acc[p][0], a[p], w0);
                ffma2(acc[p][1], a[p], w1);
                ffma2(acc[p][2], a[p], w2);
                ffma2(acc[p][3], a[p], w3);
            }
            w = wn;
        }
        __syncthreads();
    }

    #pragma unroll
    for (int p = 0; p < 4; p++) {
        float2 v0 = unpack2(acc[p][0]);
        float2 v1 = unpack2(acc[p][1]);
        float2 v2 = unpack2(acc[p][2]);
        float2 v3 = unpack2(acc[p][3]);
        int row = base + r0 + 2 * p;
        if (row < Nn) {
            *reinterpret_cast<float4*>(&g_h[row * OUT_ + c0]) =
                make_float4(v0.x, v1.x, v2.x, v3.x);
            if (WH) {
                uint2 hx;
                __half2 ha = __floats2half2_rn(v0.x, v1.x);
                __half2 hb = __floats2half2_rn(v2.x, v3.x);
                hx.x = *reinterpret_cast<unsigned*>(&ha);
                hx.y = *reinterpret_cast<unsigned*>(&hb);
                *reinterpret_cast<uint2*>(&g_hh[row * (OUT_ / 2) + c0 / 2]) = hx;
            }
        }
        if (row + 1 < Nn) {
            *reinterpret_cast<float4*>(&g_h[(row + 1) * OUT_ + c0]) =
                make_float4(v0.y, v1.y, v2.y, v3.y);
            if (WH) {
                uint2 hx;
                __half2 ha = __floats2half2_rn(v0.y, v1.y);
                __half2 hb = __floats2half2_rn(v2.y, v3.y);
                hx.x = *reinterpret_cast<unsigned*>(&ha);
                hx.y = *reinterpret_cast<unsigned*>(&hb);
                *reinterpret_cast<uint2*>(&g_hh[(row + 1) * (OUT_ / 2) + c0 / 2]) = hx;
            }
        }
    }
}

// ---------------- per-node attention logits ----------------
template <int C>
__global__ void alpha_k(const float* __restrict__ a_src, const float* __restrict__ a_dst) {
    int i = blockIdx.x * blockDim.x + threadIdx.x;
    if (i >= Nn * Hh) return;
    int node = i >> 2, head = i & 3;
    const float4* hp = reinterpret_cast<const float4*>(&g_h[node * (Hh * C) + head * C]);
    const float4* sp = reinterpret_cast<const float4*>(&a_src[head * C]);
    const float4* dp = reinterpret_cast<const float4*>(&a_dst[head * C]);
    float ss = 0.f, sd = 0.f;
    #pragma unroll
    for (int c = 0; c < C / 4; c++) {
        float4 v = hp[c];
        float4 s = __ldg(&sp[c]);
        float4 d = __ldg(&dp[c]);
        ss = fmaf(v.x, s.x, fmaf(v.y, s.y, fmaf(v.z, s.z, fmaf(v.w, s.w, ss))));
        sd = fmaf(v.x, d.x, fmaf(v.y, d.y, fmaf(v.z, d.z, fmaf(v.w, d.w, sd))));
    }
    g_as[i] = ss;
    g_ad[i] = sd;
}

// ---------------- per-edge softmax numerators (all 4 heads) ----------------
__global__ void epv_k() {
    int p = blockIdx.x * blockDim.x + threadIdx.x;
    if (p >= Ee) return;
    int src = g_csr[p];
    int dst = g_edst[p];
    float4 s = *reinterpret_cast<const float4*>(&g_as[src * Hh]);
    float4 d = *reinterpret_cast<const float4*>(&g_ad[dst * Hh]);
    float4 e = make_float4(s.x + d.x, s.y + d.y, s.z + d.z, s.w + d.w);
    e.x = (e.x < 0.f) ? 0.2f * e.x : e.x;
    e.y = (e.y < 0.f) ? 0.2f * e.y : e.y;
    e.z = (e.z < 0.f) ? 0.2f * e.z : e.z;
    e.w = (e.w < 0.f) ? 0.2f * e.w : e.w;
    *reinterpret_cast<float4*>(&g_pv[p * Hh]) =
        make_float4(__expf(e.x), __expf(e.y), __expf(e.z), __expf(e.w));
}

// ---------------- per-dst aggregation (atomic-free, float4 channels) ----------------
template <int C, bool HALF>
__global__ void __launch_bounds__(256) agg_k(const float* __restrict__ bias) {
    constexpr int HC  = Hh * C;
    constexpr int TPN = HC / 4;
    constexpr int NPB = 256 / TPN;
    int t    = threadIdx.x % TPN;
    int node = blockIdx.x * NPB + threadIdx.x / TPN;
    if (node >= Nn) return;
    int g4   = t * 4;
    int head = g4 / C;

    // implicit self-loop (fp32)
    float es = g_as[node * Hh + head] + g_ad[node * Hh + head];
    es = (es < 0.f) ? 0.2f * es : es;
    float pl = __expf(es);
    float denom = pl;
    float4 hv = *reinterpret_cast<const float4*>(&g_h[node * HC + g4]);
    float4 acc = make_float4(pl * hv.x, pl * hv.y, pl * hv.z, pl * hv.w);

    int start = g_starts[node];
    int cnt   = g_counts[node];
    #pragma unroll 4
    for (int j = 0; j < cnt; j++) {
        int   src = __ldg(&g_csr[start + j]);
        float pv  = __ldg(&g_pv[(start + j) * Hh + head]);
        float4 h;
        if (HALF) {
            uint2 raw = __ldg(reinterpret_cast<const uint2*>(&g_hh[src * (HC / 2) + t * 2]));
            __half2 ha = *reinterpret_cast<__half2*>(&raw.x);
            __half2 hb = *reinterpret_cast<__half2*>(&raw.y);
            float2 fa = __half22float2(ha);
            float2 fb = __half22float2(hb);
            h = make_float4(fa.x, fa.y, fb.x, fb.y);
        } else {
            h = *reinterpret_cast<const float4*>(&g_h[src * HC + g4]);
        }
        denom += pv;
        acc.x = fmaf(pv, h.x, acc.x);
        acc.y = fmaf(pv, h.y, acc.y);
        acc.z = fmaf(pv, h.z, acc.z);
        acc.w = fmaf(pv, h.w, acc.w);
    }
    float inv = 1.0f / denom;
    float4 b = *reinterpret_cast<const float4*>(&bias[g4]);
    float4 o;
    o.x = acc.x * inv + b.x;
    o.y = acc.y * inv + b.y;
    o.z = acc.z * inv + b.z;
    o.w = acc.w * inv + b.w;
    o.x = (o.x > 0.f) ? o.x : expm1f(o.x);
    o.y = (o.y > 0.f) ? o.y : expm1f(o.y);
    o.z = (o.z > 0.f) ? o.z : expm1f(o.z);
    o.w = (o.w > 0.f) ? o.w : expm1f(o.w);
    *reinterpret_cast<float4*>(&g_act[node * HC + g4]) = o;
}

// ---------------- fused MLP head: 256 -> 32 -> 64 -> 1 ----------------
__global__ void __launch_bounds__(256) mlp_k(const float* __restrict__ Wr,  const float* __restrict__ br,
                                             const float* __restrict__ Wf1, const float* __restrict__ bf1,
                                             const float* __restrict__ Wf2, const float* __restrict__ bf2,
                                             float* __restrict__ out) {
    __shared__ float sin_[8 * 256];
    __shared__ float smid[8 * 32];
    int w = threadIdx.x / 32, lane = threadIdx.x % 32;
    int nodeBase = blockIdx.x * 8;

    for (int idx = threadIdx.x; idx < 8 * 256; idx += 256) {
        int node = nodeBase + idx / 256;
        sin_[idx] = (node < Nn) ? g_act[node * 256 + (idx % 256)] : 0.f;
    }
    __syncthreads();

    int node = nodeBase + w;
    float acc = br[lane];
    #pragma unroll 4
    for (int k = 0; k < 256; k++) acc = fmaf(sin_[w * 256 + k], Wr[k * 32 + lane], acc);
    acc = (acc > 0.f) ? acc : expm1f(acc);
    smid[w * 32 + lane] = acc;
    __syncwarp();
    float f0 = bf1[lane], f1 = bf1[lane + 32];
    #pragma unroll
    for (int k = 0; k < 32; k++) {
        float m = smid[w * 32 + k];
        f0 = fmaf(m, Wf1[k * 64 + lane],      f0);
        f1 = fmaf(m, Wf1[k * 64 + lane + 32], f1);
    }
    f0 = (f0 > 0.f) ? f0 : expm1f(f0);
    f1 = (f1 > 0.f) ? f1 : expm1f(f1);
    float part = f0 * Wf2[lane] + f1 * Wf2[lane + 32];
    #pragma unroll
    for (int off = 16; off; off >>= 1) part += __shfl_xor_sync(0xffffffff, part, off);
    if (lane == 0 && node < Nn) out[node] = part + bf2[0];
}

// ---------------- launch ----------------
extern "C" void kernel_launch(void* const* d_in, const int* in_sizes, int n_in,
                              void* d_out, int out_size) {
    const float* x   = (const float*)d_in[0];
    const int*   ei  = (const int*)  d_in[1];
    const float* W1  = (const float*)d_in[3];
    const float* as1 = (const float*)d_in[4];
    const float* ad1 = (const float*)d_in[5];
    const float* b1  = (const float*)d_in[6];
    const float* W2  = (const float*)d_in[7];
    const float* as2 = (const float*)d_in[8];
    const float* ad2 = (const float*)d_in[9];
    const float* b2  = (const float*)d_in[10];
    const float* W3  = (const float*)d_in[11];
    const float* as3 = (const float*)d_in[12];
    const float* ad3 = (const float*)d_in[13];
    const float* b3  = (const float*)d_in[14];
    const float* W4  = (const float*)d_in[15];
    const float* as4 = (const float*)d_in[16];
    const float* ad4 = (const float*)d_in[17];
    const float* b4  = (const float*)d_in[18];
    const float* Wr  = (const float*)d_in[19];
    const float* br  = (const float*)d_in[20];
    const float* Wf1 = (const float*)d_in[21];
    const float* bf1 = (const float*)d_in[22];
    const float* Wf2 = (const float*)d_in[23];
    const float* bf2 = (const float*)d_in[24];
    float* out = (float*)d_out;

    float* actp = nullptr;
    cudaGetSymbolAddress((void**)&actp, g_act);

    const int NB_SCAN = (Nn + 1023) / 1024;
    const int EB = (Ee + 255) / 256;
    const int AB = (Nn * Hh + 255) / 256;

    // CSR build, with layer-1 GEMM in slot #4 (ncu capture slot).
    zero_k<<<(Nn + 255) / 256, 256>>>();
    hist_k<<<EB, 256>>>(ei);
    scan1_k<<<NB_SCAN, 1024>>>();
    // L1: 128 -> 32. TM=128, KC=64 -> 128-thread blocks (profiled)
    gemm_k<128, 32, 128, 64, false><<<(Nn + 127) / 128, (32 / 4) * (128 / 8)>>>(x, W1);
    scan2_k<<<1, 64>>>();
    scan3_k<<<NB_SCAN, 1024>>>();
    fill_k<<<EB, 256>>>(ei);

    // Layer 1
    alpha_k<8><<<AB, 256>>>(as1, ad1);
    epv_k<<<EB, 256>>>();
    agg_k<8, false><<<(Nn * 8 + 255) / 256, 256>>>(b1);

    // Layer 2: 32 -> 64. TM=128, KC=32 (single chunk) -> 256-thread blocks
    gemm_k<32, 64, 128, 32, false><<<(Nn + 127) / 128, (64 / 4) * (128 / 8)>>>(actp, W2);
    alpha_k<16><<<AB, 256>>>(as2, ad2);
    epv_k<<<EB, 256>>>();
    agg_k<16, false><<<(Nn * 16 + 255) / 256, 256>>>(b2);

    // Layer 3: 64 -> 128. TM=64, KC=64 (single chunk) -> 256-thread blocks, writes half
    gemm_k<64, 128, 64, 64, true><<<(Nn + 63) / 64, (128 / 4) * (64 / 8)>>>(actp, W3);
    alpha_k<32><<<AB, 256>>>(as3, ad3);
    epv_k<<<EB, 256>>>();
    agg_k<32, true><<<(Nn * 32 + 255) / 256, 256>>>(b3);

    // Layer 4: 128 -> 256. TM=32, KC=64 -> 256-thread blocks, writes half
    gemm_k<128, 256, 32, 64, true><<<(Nn + 31) / 32, (256 / 4) * (32 / 8)>>>(actp, W4);
    alpha_k<64><<<AB, 256>>>(as4, ad4);
    epv_k<<<EB, 256>>>();
    agg_k<64, true><<<(Nn * 64 + 255) / 256, 256>>>(b4);

    // MLP head
    mlp_k<<<(Nn + 7) / 8, 256>>>(Wr, br, Wf1, bf1, Wf2, bf2, out);
}